// round 2
// baseline (speedup 1.0000x reference)
#include <cuda_runtime.h>
#include <math.h>

// ---------------------------------------------------------------------------
// MotionCompensationBlock (PCD alignment): 3-level pyramid
// ---------------------------------------------------------------------------

#define CIC 16  // input channels per smem chunk in conv3x3

// scratch (sized for the largest level usage)
__device__ float g_offeat[4u * 64 * 128 * 128];
__device__ float g_om[4u * 216 * 128 * 128];
__device__ float g_samp[4u * 64 * 9 * 128 * 128];
__device__ float g_dcnout[4u * 64 * 128 * 128];
__device__ float g_low[4u * 64 * 128 * 128];
__device__ float g_up[4u * 128 * 128 * 128];

// ---------------------------------------------------------------------------
// Generic direct 3x3 conv, stride 1, pad 1. Dual-input channel concat.
// Block: 256 threads, 8x8 spatial tile x 32 output channels.
// ---------------------------------------------------------------------------
__global__ void __launch_bounds__(256)
conv3x3_tiled(const float* __restrict__ in1, int c1, long bs1,
              const float* __restrict__ in2, int c2, long bs2,
              const float* __restrict__ w, const float* __restrict__ bias,
              float* __restrict__ out, int Cout, int H, int W)
{
    __shared__ float s_in[CIC][10][10];
    __shared__ float s_w[CIC * 9][32];

    const int tid = threadIdx.x;
    const int nOcBlk = (Cout + 31) >> 5;
    const int b = blockIdx.z / nOcBlk;
    const int ocb = blockIdx.z % nOcBlk;
    const int x0 = blockIdx.x * 8, y0 = blockIdx.y * 8;
    const int Cin = c1 + c2;
    const int HW = H * W;

    const int pix = tid & 63;
    const int px = pix & 7, py = pix >> 3;
    const int ocg = tid >> 6;  // 0..3, each handles 8 consecutive ocs

    float acc[8];
#pragma unroll
    for (int j = 0; j < 8; j++) acc[j] = 0.f;

    for (int ic0 = 0; ic0 < Cin; ic0 += CIC) {
        __syncthreads();
        // stage input tile (with halo)
        for (int e = tid; e < CIC * 100; e += 256) {
            int ic = e / 100;
            int rr = (e % 100) / 10;
            int cc = e % 10;
            int gy = y0 + rr - 1, gx = x0 + cc - 1;
            int ch = ic0 + ic;
            float v = 0.f;
            if (ch < Cin && gy >= 0 && gy < H && gx >= 0 && gx < W) {
                if (ch < c1) v = in1[(long)b * bs1 + (long)ch * HW + gy * W + gx];
                else         v = in2[(long)b * bs2 + (long)(ch - c1) * HW + gy * W + gx];
            }
            s_in[ic][rr][cc] = v;
        }
        // stage weights transposed: s_w[ic*9+k][oc]
        for (int e = tid; e < CIC * 9 * 32; e += 256) {
            int oc = e & 31;
            int r = e >> 5;  // ic*9 + k
            int goc = ocb * 32 + oc;
            int gic = ic0 + r / 9;
            float v = 0.f;
            if (goc < Cout && gic < Cin)
                v = w[((long)goc * Cin + gic) * 9 + (r % 9)];
            s_w[r][oc] = v;
        }
        __syncthreads();

#pragma unroll 2
        for (int ic = 0; ic < CIC; ic++) {
#pragma unroll
            for (int t = 0; t < 9; t++) {
                float v = s_in[ic][py + t / 3][px + t % 3];
                const float4 wa = *(const float4*)&s_w[ic * 9 + t][ocg * 8];
                const float4 wb = *(const float4*)&s_w[ic * 9 + t][ocg * 8 + 4];
                acc[0] += v * wa.x; acc[1] += v * wa.y;
                acc[2] += v * wa.z; acc[3] += v * wa.w;
                acc[4] += v * wb.x; acc[5] += v * wb.y;
                acc[6] += v * wb.z; acc[7] += v * wb.w;
            }
        }
    }

#pragma unroll
    for (int j = 0; j < 8; j++) {
        int oc = ocb * 32 + ocg * 8 + j;
        if (oc < Cout)
            out[((long)b * Cout + oc) * HW + (y0 + py) * W + (x0 + px)] = acc[j] + bias[oc];
    }
}

// ---------------------------------------------------------------------------
// 1x1 GEMM over pixels: out[b,oc,p] = bias[oc] + sum_ic in[b,ic,p] * w[oc,ic]
// ---------------------------------------------------------------------------
__global__ void __launch_bounds__(256)
gemm1x1(const float* __restrict__ in, const float* __restrict__ w,
        const float* __restrict__ bias, float* __restrict__ out,
        int Cin, int Cout, int HW)
{
    __shared__ float s_in[32][64];
    __shared__ float s_w[32][32];

    const int tid = threadIdx.x;
    const int p0 = blockIdx.x * 64;
    const int ocb = blockIdx.y;
    const int b = blockIdx.z;
    const int pix = tid & 63;
    const int ocg = tid >> 6;

    float acc[8];
#pragma unroll
    for (int j = 0; j < 8; j++) acc[j] = 0.f;

    for (int ic0 = 0; ic0 < Cin; ic0 += 32) {
        __syncthreads();
        for (int e = tid; e < 32 * 64; e += 256) {
            int ic = e >> 6, p = e & 63;
            int gic = ic0 + ic;
            s_in[ic][p] = (gic < Cin) ? in[((long)b * Cin + gic) * HW + p0 + p] : 0.f;
        }
        for (int e = tid; e < 32 * 32; e += 256) {
            int oc = e & 31, ic = e >> 5;
            int goc = ocb * 32 + oc, gic = ic0 + ic;
            s_w[ic][oc] = (goc < Cout && gic < Cin) ? w[(long)goc * Cin + gic] : 0.f;
        }
        __syncthreads();

#pragma unroll 4
        for (int ic = 0; ic < 32; ic++) {
            float v = s_in[ic][pix];
            const float4 wa = *(const float4*)&s_w[ic][ocg * 8];
            const float4 wb = *(const float4*)&s_w[ic][ocg * 8 + 4];
            acc[0] += v * wa.x; acc[1] += v * wa.y;
            acc[2] += v * wa.z; acc[3] += v * wa.w;
            acc[4] += v * wb.x; acc[5] += v * wb.y;
            acc[6] += v * wb.z; acc[7] += v * wb.w;
        }
    }

#pragma unroll
    for (int j = 0; j < 8; j++) {
        int oc = ocb * 32 + ocg * 8 + j;
        if (oc < Cout)
            out[((long)b * Cout + oc) * HW + p0 + pix] = acc[j] + bias[oc];
    }
}

// ---------------------------------------------------------------------------
// DCN bilinear sampling with 8 deformable groups, 9 taps, sigmoid mask.
// samp channel layout: (g*Cg + c)*9 + k
// ---------------------------------------------------------------------------
__global__ void dcn_sample(const float* __restrict__ x, long xbs,
                           const float* __restrict__ om,
                           float* __restrict__ samp,
                           int C, int H, int W, int total)
{
    int idx = blockIdx.x * blockDim.x + threadIdx.x;
    if (idx >= total) return;
    const int HW = H * W;
    const int p = idx % HW;
    const int k = (idx / HW) % 9;
    const int g = (idx / (HW * 9)) % 8;
    const int b = idx / (HW * 72);
    const int y = p / W, xq = p % W;

    const long omb = (long)b * 216 * HW + (long)(g * 9 + k) * HW + p;
    float dy = om[omb];
    float dx = om[omb + 72L * HW];
    float mk = om[omb + 144L * HW];
    mk = 1.f / (1.f + expf(-mk));

    float pyf = (float)y + (float)(k / 3 - 1) + dy;
    float pxf = (float)xq + (float)(k % 3 - 1) + dx;
    float y0f = floorf(pyf), x0f = floorf(pxf);
    int y0 = (int)y0f, x0i = (int)x0f;
    float ty = pyf - y0f, tx = pxf - x0f;
    int y1 = y0 + 1, x1i = x0i + 1;

    bool vy0 = (y0 >= 0) && (y0 < H), vy1 = (y1 >= 0) && (y1 < H);
    bool vx0 = (x0i >= 0) && (x0i < W), vx1 = (x1i >= 0) && (x1i < W);
    float w00 = (vy0 && vx0) ? (1.f - ty) * (1.f - tx) : 0.f;
    float w01 = (vy0 && vx1) ? (1.f - ty) * tx : 0.f;
    float w10 = (vy1 && vx0) ? ty * (1.f - tx) : 0.f;
    float w11 = (vy1 && vx1) ? ty * tx : 0.f;

    int cy0 = min(max(y0, 0), H - 1), cy1 = min(max(y1, 0), H - 1);
    int cx0 = min(max(x0i, 0), W - 1), cx1 = min(max(x1i, 0), W - 1);
    int i00 = cy0 * W + cx0, i01 = cy0 * W + cx1;
    int i10 = cy1 * W + cx0, i11 = cy1 * W + cx1;

    const int Cg = C >> 3;
    const float* xb = x + (long)b * xbs + (long)g * Cg * HW;
    float* sp = samp + ((long)b * C + (long)g * Cg) * 9 * HW + (long)k * HW + p;

    for (int c = 0; c < Cg; c++) {
        const float* xc = xb + (long)c * HW;
        float v = w00 * xc[i00] + w01 * xc[i01] + w10 * xc[i10] + w11 * xc[i11];
        sp[(long)c * 9 * HW] = v * mk;
    }
}

// ---------------------------------------------------------------------------
// Bilinear 2x upsample, align_corners=False
// ---------------------------------------------------------------------------
__global__ void up2_kernel(const float* __restrict__ in, float* __restrict__ out,
                           int H, int W, int total)
{
    int idx = blockIdx.x * blockDim.x + threadIdx.x;
    if (idx >= total) return;
    const int W2 = 2 * W, H2 = 2 * H;
    const int ox = idx % W2;
    const int oy = (idx / W2) % H2;
    const int bc = idx / (W2 * H2);

    float sy = fmaxf(oy * 0.5f - 0.25f, 0.f);
    float sx = fmaxf(ox * 0.5f - 0.25f, 0.f);
    int y0 = (int)floorf(sy); float ty = sy - (float)y0; int y1 = min(y0 + 1, H - 1);
    int x0 = (int)floorf(sx); float tx = sx - (float)x0; int x1 = min(x0 + 1, W - 1);

    const float* p = in + (long)bc * H * W;
    float a = p[y0 * W + x0] * (1.f - ty) + p[y1 * W + x0] * ty;
    float c = p[y0 * W + x1] * (1.f - ty) + p[y1 * W + x1] * ty;
    out[idx] = a * (1.f - tx) + c * tx;
}

// ---------------------------------------------------------------------------
extern "C" void kernel_launch(void* const* d_in, const int* in_sizes, int n_in,
                              void* d_out, int out_size)
{
    // Resolve x0..x2 / flow0..flow2 among the first 6 inputs BY SIZE
    // (metadata order is x0,flow0,x1,flow1,x2,flow2 — dict insertion order).
    const float *x0 = nullptr, *x1 = nullptr, *x2 = nullptr;
    const float *flow0 = nullptr, *flow1 = nullptr, *flow2 = nullptr;
    for (int i = 0; i < 6; i++) {
        const float* p = (const float*)d_in[i];
        switch (in_sizes[i]) {
            case 4 * 2 * 64 * 128 * 128: x0 = p; break;     // 8388608
            case 4 * 2 * 128 * 64 * 64:  x1 = p; break;     // 4194304
            case 4 * 2 * 256 * 32 * 32:  x2 = p; break;     // 2097152
            case 4 * 2 * 128 * 128:      flow0 = p; break;  // 131072
            case 4 * 2 * 64 * 64:        flow1 = p; break;  // 32768
            case 4 * 2 * 32 * 32:        flow2 = p; break;  // 8192
        }
    }

    const float* off_w0 = (const float*)d_in[6];  const float* off_b0 = (const float*)d_in[7];
    const float* co_w0  = (const float*)d_in[8];  const float* co_b0  = (const float*)d_in[9];
    const float* dcn_w0 = (const float*)d_in[10]; const float* dcn_b0 = (const float*)d_in[11];
    const float* off_w1 = (const float*)d_in[12]; const float* off_b1 = (const float*)d_in[13];
    const float* co_w1  = (const float*)d_in[14]; const float* co_b1  = (const float*)d_in[15];
    const float* dcn_w1 = (const float*)d_in[16]; const float* dcn_b1 = (const float*)d_in[17];
    const float* off_w2 = (const float*)d_in[18]; const float* off_b2 = (const float*)d_in[19];
    const float* co_w2  = (const float*)d_in[20]; const float* co_b2  = (const float*)d_in[21];
    const float* dcn_w2 = (const float*)d_in[22]; const float* dcn_b2 = (const float*)d_in[23];
    const float* ch_w0  = (const float*)d_in[24]; const float* ch_b0  = (const float*)d_in[25];
    const float* ft_w0  = (const float*)d_in[26]; const float* ft_b0  = (const float*)d_in[27];
    const float* ch_w1  = (const float*)d_in[28]; const float* ch_b1  = (const float*)d_in[29];
    const float* ft_w1  = (const float*)d_in[30]; const float* ft_b1  = (const float*)d_in[31];

    float *offeat, *om, *samp, *dcnout, *low, *up;
    cudaGetSymbolAddress((void**)&offeat, g_offeat);
    cudaGetSymbolAddress((void**)&om,     g_om);
    cudaGetSymbolAddress((void**)&samp,   g_samp);
    cudaGetSymbolAddress((void**)&dcnout, g_dcnout);
    cudaGetSymbolAddress((void**)&low,    g_low);
    cudaGetSymbolAddress((void**)&up,     g_up);

    float* out0 = (float*)d_out;                    // (4,64,128,128)
    float* out1 = out0 + 4L * 64 * 128 * 128;       // (4,128,64,64)
    float* out2 = out1 + 4L * 128 * 64 * 64;        // (4,256,32,32)

    const int B = 4;

    // ================= level 2 (coarsest): C=256, 32x32 =================
    {
        const int H = 32, W = 32, HW = H * W;
        conv3x3_tiled<<<dim3(W / 8, H / 8, B * 8), 256>>>(
            x2, 512, 512L * HW, flow2, 2, 2L * HW,
            off_w2, off_b2, offeat, 256, H, W);
        conv3x3_tiled<<<dim3(W / 8, H / 8, B * 7), 256>>>(
            offeat, 256, 256L * HW, nullptr, 0, 0,
            co_w2, co_b2, om, 216, H, W);
        int total = B * 72 * HW;
        dcn_sample<<<(total + 255) / 256, 256>>>(
            x2 + 256L * HW, 512L * HW, om, samp, 256, H, W, total);
        gemm1x1<<<dim3(HW / 64, 8, B), 256>>>(samp, dcn_w2, dcn_b2, out2, 2304, 256, HW);
        int ut = B * 256 * 4 * HW;
        up2_kernel<<<(ut + 255) / 256, 256>>>(out2, up, H, W, ut);
    }

    // ================= level 1: C=128, 64x64 =================
    {
        const int H = 64, W = 64, HW = H * W;
        conv3x3_tiled<<<dim3(W / 8, H / 8, B * 4), 256>>>(
            x1, 256, 256L * HW, flow1, 2, 2L * HW,
            off_w1, off_b1, offeat, 128, H, W);
        conv3x3_tiled<<<dim3(W / 8, H / 8, B * 7), 256>>>(
            offeat, 128, 128L * HW, nullptr, 0, 0,
            co_w1, co_b1, om, 216, H, W);
        int total = B * 72 * HW;
        dcn_sample<<<(total + 255) / 256, 256>>>(
            x1 + 128L * HW, 256L * HW, om, samp, 128, H, W, total);
        gemm1x1<<<dim3(HW / 64, 4, B), 256>>>(samp, dcn_w1, dcn_b1, dcnout, 1152, 128, HW);
        conv3x3_tiled<<<dim3(W / 8, H / 8, B * 4), 256>>>(
            up, 256, 256L * HW, nullptr, 0, 0,
            ch_w1, ch_b1, low, 128, H, W);
        conv3x3_tiled<<<dim3(W / 8, H / 8, B * 4), 256>>>(
            dcnout, 128, 128L * HW, low, 128, 128L * HW,
            ft_w1, ft_b1, out1, 128, H, W);
        int ut = B * 128 * 4 * HW;
        up2_kernel<<<(ut + 255) / 256, 256>>>(out1, up, H, W, ut);
    }

    // ================= level 0 (finest): C=64, 128x128 =================
    {
        const int H = 128, W = 128, HW = H * W;
        conv3x3_tiled<<<dim3(W / 8, H / 8, B * 2), 256>>>(
            x0, 128, 128L * HW, flow0, 2, 2L * HW,
            off_w0, off_b0, offeat, 64, H, W);
        conv3x3_tiled<<<dim3(W / 8, H / 8, B * 7), 256>>>(
            offeat, 64, 64L * HW, nullptr, 0, 0,
            co_w0, co_b0, om, 216, H, W);
        int total = B * 72 * HW;
        dcn_sample<<<(total + 255) / 256, 256>>>(
            x0 + 64L * HW, 128L * HW, om, samp, 64, H, W, total);
        gemm1x1<<<dim3(HW / 64, 2, B), 256>>>(samp, dcn_w0, dcn_b0, dcnout, 576, 64, HW);
        conv3x3_tiled<<<dim3(W / 8, H / 8, B * 2), 256>>>(
            up, 128, 128L * HW, nullptr, 0, 0,
            ch_w0, ch_b0, low, 64, H, W);
        conv3x3_tiled<<<dim3(W / 8, H / 8, B * 2), 256>>>(
            dcnout, 64, 64L * HW, low, 64, 64L * HW,
            ft_w0, ft_b0, out0, 64, H, W);
    }
}

// round 4
// speedup vs baseline: 1.5725x; 1.5725x over previous
#include <cuda_runtime.h>
#include <math.h>

// ---------------------------------------------------------------------------
// MotionCompensationBlock (PCD alignment): 3-level pyramid
// Round 4 (= round 3 resubmit after infra failure):
// register-tiled conv3x3 + gemm1x1 (L1-port pressure /3..4)
// ---------------------------------------------------------------------------

#define CIC 8  // input channels per smem chunk in conv3x3

// scratch
__device__ float g_offeat[4u * 64 * 128 * 128];
__device__ float g_om[4u * 216 * 128 * 128];
__device__ float g_samp[4u * 64 * 9 * 128 * 128];
__device__ float g_dcnout[4u * 64 * 128 * 128];
__device__ float g_low[4u * 64 * 128 * 128];
__device__ float g_up[4u * 128 * 128 * 128];

// ---------------------------------------------------------------------------
// Direct 3x3 conv, stride 1, pad 1, dual-input channel concat.
// Block: 256 thr = 16x16 spatial tile x 32 ocs.
// Thread: 2x2 pixels x 8 ocs (32 accums), input patch register-cached.
// ---------------------------------------------------------------------------
__global__ void __launch_bounds__(256)
conv3x3_v2(const float* __restrict__ in1, int c1, long bs1,
           const float* __restrict__ in2, int c2, long bs2,
           const float* __restrict__ w, const float* __restrict__ bias,
           float* __restrict__ out, int Cout, int H, int W)
{
    __shared__ float s_in[CIC][18][20];   // 18x18 tile (+halo), padded row
    __shared__ float s_w[CIC * 9][32];    // transposed weights

    const int tid = threadIdx.x;
    const int nOcBlk = (Cout + 31) >> 5;
    const int b = blockIdx.z / nOcBlk;
    const int ocb = blockIdx.z % nOcBlk;
    const int x0 = blockIdx.x * 16, y0 = blockIdx.y * 16;
    const int Cin = c1 + c2;
    const int HW = H * W;

    const int q = tid & 63;        // 8x8 quads
    const int qx = (q & 7) * 2;
    const int qy = (q >> 3) * 2;
    const int ocg = tid >> 6;      // 4 groups of 8 ocs

    float acc[4][8];
#pragma unroll
    for (int i = 0; i < 4; i++)
#pragma unroll
        for (int j = 0; j < 8; j++) acc[i][j] = 0.f;

    for (int ic0 = 0; ic0 < Cin; ic0 += CIC) {
        __syncthreads();
        // stage 18x18 input tile with halo
        for (int e = tid; e < CIC * 18 * 18; e += 256) {
            int ic = e / 324;
            int rr = (e % 324) / 18;
            int cc = e % 18;
            int gy = y0 + rr - 1, gx = x0 + cc - 1;
            int ch = ic0 + ic;
            float v = 0.f;
            if (ch < Cin && gy >= 0 && gy < H && gx >= 0 && gx < W) {
                if (ch < c1) v = in1[(long)b * bs1 + (long)ch * HW + gy * W + gx];
                else         v = in2[(long)b * bs2 + (long)(ch - c1) * HW + gy * W + gx];
            }
            s_in[ic][rr][cc] = v;
        }
        // stage weights transposed: s_w[ic*9+k][oc]
        for (int e = tid; e < CIC * 9 * 32; e += 256) {
            int oc = e & 31;
            int r = e >> 5;  // ic*9 + k
            int goc = ocb * 32 + oc;
            int gic = ic0 + r / 9;
            float v = 0.f;
            if (goc < Cout && gic < Cin)
                v = w[((long)goc * Cin + gic) * 9 + (r % 9)];
            s_w[r][oc] = v;
        }
        __syncthreads();

#pragma unroll
        for (int ic = 0; ic < CIC; ic++) {
            // register-cache the 4x4 input patch for this ic
            float rr[4][4];
#pragma unroll
            for (int r = 0; r < 4; r++) {
                float2 a  = *(const float2*)&s_in[ic][qy + r][qx];
                float2 b2 = *(const float2*)&s_in[ic][qy + r][qx + 2];
                rr[r][0] = a.x; rr[r][1] = a.y; rr[r][2] = b2.x; rr[r][3] = b2.y;
            }
#pragma unroll
            for (int t = 0; t < 9; t++) {
                const int ty = t / 3, tx = t % 3;
                const float4 wa = *(const float4*)&s_w[ic * 9 + t][ocg * 8];
                const float4 wb = *(const float4*)&s_w[ic * 9 + t][ocg * 8 + 4];
                const float i00 = rr[ty][tx],     i01 = rr[ty][tx + 1];
                const float i10 = rr[ty + 1][tx], i11 = rr[ty + 1][tx + 1];
                float wv[8] = {wa.x, wa.y, wa.z, wa.w, wb.x, wb.y, wb.z, wb.w};
#pragma unroll
                for (int j = 0; j < 8; j++) {
                    acc[0][j] += i00 * wv[j];
                    acc[1][j] += i01 * wv[j];
                    acc[2][j] += i10 * wv[j];
                    acc[3][j] += i11 * wv[j];
                }
            }
        }
    }

#pragma unroll
    for (int j = 0; j < 8; j++) {
        int oc = ocb * 32 + ocg * 8 + j;
        if (oc < Cout) {
            const float bb = bias[oc];
            long base = ((long)b * Cout + oc) * HW;
            float2 v0 = make_float2(acc[0][j] + bb, acc[1][j] + bb);
            float2 v1 = make_float2(acc[2][j] + bb, acc[3][j] + bb);
            *(float2*)&out[base + (long)(y0 + qy)     * W + (x0 + qx)] = v0;
            *(float2*)&out[base + (long)(y0 + qy + 1) * W + (x0 + qx)] = v1;
        }
    }
}

// ---------------------------------------------------------------------------
// 1x1 GEMM over pixels. Block: 256 thr = 64px x 64oc tile; thread: 4px x 4oc.
// Requires: Cin % 16 == 0, Cout % 64 == 0, HW % 64 == 0. (All hold here.)
// ---------------------------------------------------------------------------
__global__ void __launch_bounds__(256)
gemm1x1_v2(const float* __restrict__ in, const float* __restrict__ w,
           const float* __restrict__ bias, float* __restrict__ out,
           int Cin, int Cout, int HW)
{
    __shared__ float s_in[16][64];
    __shared__ float s_w[16][64];

    const int tid = threadIdx.x;
    const int p0 = blockIdx.x * 64;
    const int ocb = blockIdx.y;
    const int b = blockIdx.z;
    const int pxg = tid & 15;   // 16 pixel groups of 4
    const int ocg = tid >> 4;   // 16 oc groups of 4

    float acc[4][4];
#pragma unroll
    for (int i = 0; i < 4; i++)
#pragma unroll
        for (int j = 0; j < 4; j++) acc[i][j] = 0.f;

    for (int ic0 = 0; ic0 < Cin; ic0 += 16) {
        __syncthreads();
#pragma unroll
        for (int e = tid; e < 1024; e += 256) {
            int ic = e >> 6, p = e & 63;
            s_in[ic][p] = in[((long)b * Cin + ic0 + ic) * HW + p0 + p];
        }
#pragma unroll
        for (int e = tid; e < 1024; e += 256) {
            int oc = e & 63, ic = e >> 6;
            s_w[ic][oc] = w[(long)(ocb * 64 + oc) * Cin + ic0 + ic];
        }
        __syncthreads();

#pragma unroll
        for (int ic = 0; ic < 16; ic++) {
            const float4 vi = *(const float4*)&s_in[ic][pxg * 4];
            const float4 vw = *(const float4*)&s_w[ic][ocg * 4];
            float iv[4] = {vi.x, vi.y, vi.z, vi.w};
            float wv[4] = {vw.x, vw.y, vw.z, vw.w};
#pragma unroll
            for (int i = 0; i < 4; i++)
#pragma unroll
                for (int j = 0; j < 4; j++)
                    acc[i][j] += iv[i] * wv[j];
        }
    }

#pragma unroll
    for (int j = 0; j < 4; j++) {
        int oc = ocb * 64 + ocg * 4 + j;
        const float bb = bias[oc];
        float4 v = make_float4(acc[0][j] + bb, acc[1][j] + bb,
                               acc[2][j] + bb, acc[3][j] + bb);
        *(float4*)&out[((long)b * Cout + oc) * HW + p0 + pxg * 4] = v;
    }
}

// ---------------------------------------------------------------------------
// DCN bilinear sampling (8 groups, 9 taps, sigmoid mask).
// samp channel layout: (g*Cg + c)*9 + k
// ---------------------------------------------------------------------------
__global__ void dcn_sample(const float* __restrict__ x, long xbs,
                           const float* __restrict__ om,
                           float* __restrict__ samp,
                           int C, int H, int W, int total)
{
    int idx = blockIdx.x * blockDim.x + threadIdx.x;
    if (idx >= total) return;
    const int HW = H * W;
    const int p = idx % HW;
    const int k = (idx / HW) % 9;
    const int g = (idx / (HW * 9)) % 8;
    const int b = idx / (HW * 72);
    const int y = p / W, xq = p % W;

    const long omb = (long)b * 216 * HW + (long)(g * 9 + k) * HW + p;
    float dy = om[omb];
    float dx = om[omb + 72L * HW];
    float mk = om[omb + 144L * HW];
    mk = 1.f / (1.f + expf(-mk));

    float pyf = (float)y + (float)(k / 3 - 1) + dy;
    float pxf = (float)xq + (float)(k % 3 - 1) + dx;
    float y0f = floorf(pyf), x0f = floorf(pxf);
    int y0 = (int)y0f, x0i = (int)x0f;
    float ty = pyf - y0f, tx = pxf - x0f;
    int y1 = y0 + 1, x1i = x0i + 1;

    bool vy0 = (y0 >= 0) && (y0 < H), vy1 = (y1 >= 0) && (y1 < H);
    bool vx0 = (x0i >= 0) && (x0i < W), vx1 = (x1i >= 0) && (x1i < W);
    float w00 = (vy0 && vx0) ? (1.f - ty) * (1.f - tx) : 0.f;
    float w01 = (vy0 && vx1) ? (1.f - ty) * tx : 0.f;
    float w10 = (vy1 && vx0) ? ty * (1.f - tx) : 0.f;
    float w11 = (vy1 && vx1) ? ty * tx : 0.f;

    int cy0 = min(max(y0, 0), H - 1), cy1 = min(max(y1, 0), H - 1);
    int cx0 = min(max(x0i, 0), W - 1), cx1 = min(max(x1i, 0), W - 1);
    int i00 = cy0 * W + cx0, i01 = cy0 * W + cx1;
    int i10 = cy1 * W + cx0, i11 = cy1 * W + cx1;

    const int Cg = C >> 3;
    const float* xb = x + (long)b * xbs + (long)g * Cg * HW;
    float* sp = samp + ((long)b * C + (long)g * Cg) * 9 * HW + (long)k * HW + p;

    for (int c = 0; c < Cg; c++) {
        const float* xc = xb + (long)c * HW;
        float v = w00 * xc[i00] + w01 * xc[i01] + w10 * xc[i10] + w11 * xc[i11];
        sp[(long)c * 9 * HW] = v * mk;
    }
}

// ---------------------------------------------------------------------------
// Bilinear 2x upsample, align_corners=False (torch semantics)
// ---------------------------------------------------------------------------
__global__ void up2_kernel(const float* __restrict__ in, float* __restrict__ out,
                           int H, int W, int total)
{
    int idx = blockIdx.x * blockDim.x + threadIdx.x;
    if (idx >= total) return;
    const int W2 = 2 * W, H2 = 2 * H;
    const int ox = idx % W2;
    const int oy = (idx / W2) % H2;
    const int bc = idx / (W2 * H2);

    float sy = fmaxf(oy * 0.5f - 0.25f, 0.f);
    float sx = fmaxf(ox * 0.5f - 0.25f, 0.f);
    int y0 = (int)floorf(sy); float ty = sy - (float)y0; int y1 = min(y0 + 1, H - 1);
    int x0 = (int)floorf(sx); float tx = sx - (float)x0; int x1 = min(x0 + 1, W - 1);

    const float* p = in + (long)bc * H * W;
    float a = p[y0 * W + x0] * (1.f - ty) + p[y1 * W + x0] * ty;
    float c = p[y0 * W + x1] * (1.f - ty) + p[y1 * W + x1] * ty;
    out[idx] = a * (1.f - tx) + c * tx;
}

// ---------------------------------------------------------------------------
extern "C" void kernel_launch(void* const* d_in, const int* in_sizes, int n_in,
                              void* d_out, int out_size)
{
    // Resolve x / flow tensors by element count (robust to metadata order).
    const float *x0 = nullptr, *x1 = nullptr, *x2 = nullptr;
    const float *flow0 = nullptr, *flow1 = nullptr, *flow2 = nullptr;
    for (int i = 0; i < 6; i++) {
        const float* p = (const float*)d_in[i];
        switch (in_sizes[i]) {
            case 4 * 2 * 64 * 128 * 128: x0 = p; break;
            case 4 * 2 * 128 * 64 * 64:  x1 = p; break;
            case 4 * 2 * 256 * 32 * 32:  x2 = p; break;
            case 4 * 2 * 128 * 128:      flow0 = p; break;
            case 4 * 2 * 64 * 64:        flow1 = p; break;
            case 4 * 2 * 32 * 32:        flow2 = p; break;
        }
    }

    const float* off_w0 = (const float*)d_in[6];  const float* off_b0 = (const float*)d_in[7];
    const float* co_w0  = (const float*)d_in[8];  const float* co_b0  = (const float*)d_in[9];
    const float* dcn_w0 = (const float*)d_in[10]; const float* dcn_b0 = (const float*)d_in[11];
    const float* off_w1 = (const float*)d_in[12]; const float* off_b1 = (const float*)d_in[13];
    const float* co_w1  = (const float*)d_in[14]; const float* co_b1  = (const float*)d_in[15];
    const float* dcn_w1 = (const float*)d_in[16]; const float* dcn_b1 = (const float*)d_in[17];
    const float* off_w2 = (const float*)d_in[18]; const float* off_b2 = (const float*)d_in[19];
    const float* co_w2  = (const float*)d_in[20]; const float* co_b2  = (const float*)d_in[21];
    const float* dcn_w2 = (const float*)d_in[22]; const float* dcn_b2 = (const float*)d_in[23];
    const float* ch_w0  = (const float*)d_in[24]; const float* ch_b0  = (const float*)d_in[25];
    const float* ft_w0  = (const float*)d_in[26]; const float* ft_b0  = (const float*)d_in[27];
    const float* ch_w1  = (const float*)d_in[28]; const float* ch_b1  = (const float*)d_in[29];
    const float* ft_w1  = (const float*)d_in[30]; const float* ft_b1  = (const float*)d_in[31];

    float *offeat, *om, *samp, *dcnout, *low, *up;
    cudaGetSymbolAddress((void**)&offeat, g_offeat);
    cudaGetSymbolAddress((void**)&om,     g_om);
    cudaGetSymbolAddress((void**)&samp,   g_samp);
    cudaGetSymbolAddress((void**)&dcnout, g_dcnout);
    cudaGetSymbolAddress((void**)&low,    g_low);
    cudaGetSymbolAddress((void**)&up,     g_up);

    float* out0 = (float*)d_out;                    // (4,64,128,128)
    float* out1 = out0 + 4L * 64 * 128 * 128;       // (4,128,64,64)
    float* out2 = out1 + 4L * 128 * 64 * 64;        // (4,256,32,32)

    const int B = 4;

    // ================= level 2 (coarsest): C=256, 32x32 =================
    {
        const int H = 32, W = 32, HW = H * W;
        conv3x3_v2<<<dim3(W / 16, H / 16, B * 8), 256>>>(
            x2, 512, 512L * HW, flow2, 2, 2L * HW,
            off_w2, off_b2, offeat, 256, H, W);
        conv3x3_v2<<<dim3(W / 16, H / 16, B * 7), 256>>>(
            offeat, 256, 256L * HW, nullptr, 0, 0,
            co_w2, co_b2, om, 216, H, W);
        int total = B * 72 * HW;
        dcn_sample<<<(total + 255) / 256, 256>>>(
            x2 + 256L * HW, 512L * HW, om, samp, 256, H, W, total);
        gemm1x1_v2<<<dim3(HW / 64, 4, B), 256>>>(samp, dcn_w2, dcn_b2, out2, 2304, 256, HW);
        int ut = B * 256 * 4 * HW;
        up2_kernel<<<(ut + 255) / 256, 256>>>(out2, up, H, W, ut);
    }

    // ================= level 1: C=128, 64x64 =================
    {
        const int H = 64, W = 64, HW = H * W;
        conv3x3_v2<<<dim3(W / 16, H / 16, B * 4), 256>>>(
            x1, 256, 256L * HW, flow1, 2, 2L * HW,
            off_w1, off_b1, offeat, 128, H, W);
        conv3x3_v2<<<dim3(W / 16, H / 16, B * 7), 256>>>(
            offeat, 128, 128L * HW, nullptr, 0, 0,
            co_w1, co_b1, om, 216, H, W);
        int total = B * 72 * HW;
        dcn_sample<<<(total + 255) / 256, 256>>>(
            x1 + 128L * HW, 256L * HW, om, samp, 128, H, W, total);
        gemm1x1_v2<<<dim3(HW / 64, 2, B), 256>>>(samp, dcn_w1, dcn_b1, dcnout, 1152, 128, HW);
        conv3x3_v2<<<dim3(W / 16, H / 16, B * 4), 256>>>(
            up, 256, 256L * HW, nullptr, 0, 0,
            ch_w1, ch_b1, low, 128, H, W);
        conv3x3_v2<<<dim3(W / 16, H / 16, B * 4), 256>>>(
            dcnout, 128, 128L * HW, low, 128, 128L * HW,
            ft_w1, ft_b1, out1, 128, H, W);
        int ut = B * 128 * 4 * HW;
        up2_kernel<<<(ut + 255) / 256, 256>>>(out1, up, H, W, ut);
    }

    // ================= level 0 (finest): C=64, 128x128 =================
    {
        const int H = 128, W = 128, HW = H * W;
        conv3x3_v2<<<dim3(W / 16, H / 16, B * 2), 256>>>(
            x0, 128, 128L * HW, flow0, 2, 2L * HW,
            off_w0, off_b0, offeat, 64, H, W);
        conv3x3_v2<<<dim3(W / 16, H / 16, B * 7), 256>>>(
            offeat, 64, 64L * HW, nullptr, 0, 0,
            co_w0, co_b0, om, 216, H, W);
        int total = B * 72 * HW;
        dcn_sample<<<(total + 255) / 256, 256>>>(
            x0 + 64L * HW, 128L * HW, om, samp, 64, H, W, total);
        gemm1x1_v2<<<dim3(HW / 64, 1, B), 256>>>(samp, dcn_w0, dcn_b0, dcnout, 576, 64, HW);
        conv3x3_v2<<<dim3(W / 16, H / 16, B * 2), 256>>>(
            up, 128, 128L * HW, nullptr, 0, 0,
            ch_w0, ch_b0, low, 64, H, W);
        conv3x3_v2<<<dim3(W / 16, H / 16, B * 2), 256>>>(
            dcnout, 64, 64L * HW, low, 64, 64L * HW,
            ft_w0, ft_b0, out0, 64, H, W);
    }
}

// round 6
// speedup vs baseline: 1.9819x; 1.2604x over previous
#include <cuda_runtime.h>
#include <cuda_bf16.h>
#include <math.h>
#include <stdint.h>

// ===========================================================================
// MotionCompensationBlock — mma.sync (HMMA bf16x3 hi/lo) implicit-GEMM
// (tcgen05 unavailable: harness compiles via compute_100, no 'a' features)
// ===========================================================================

__device__ __forceinline__ uint32_t smem_u32(const void* p) {
    uint32_t a;
    asm("{ .reg .u64 t; cvta.to.shared.u64 t, %1; cvt.u32.u64 %0, t; }" : "=r"(a) : "l"(p));
    return a;
}

#define CP16(dst, src) \
    asm volatile("cp.async.cg.shared.global [%0], [%1], 16;" :: "r"(dst), "l"(src) : "memory")
#define CP_COMMIT() asm volatile("cp.async.commit_group;" ::: "memory")
#define CP_WAIT(n)  asm volatile("cp.async.wait_group %0;" :: "n"(n) : "memory")

__device__ __forceinline__ void mma16816(float* c, uint32_t a0, uint32_t a1,
                                         uint32_t a2, uint32_t a3,
                                         uint32_t b0, uint32_t b1) {
    asm volatile(
        "mma.sync.aligned.m16n8k16.row.col.f32.bf16.bf16.f32 "
        "{%0,%1,%2,%3}, {%4,%5,%6,%7}, {%8,%9}, {%0,%1,%2,%3};"
        : "+f"(c[0]), "+f"(c[1]), "+f"(c[2]), "+f"(c[3])
        : "r"(a0), "r"(a1), "r"(a2), "r"(a3), "r"(b0), "r"(b1));
}

// ------------------------------ scratch -----------------------------------
__device__ __nv_bfloat16 g_Bhi[83886080];   // 160MB : max Npix*Kp (level0 off)
__device__ __nv_bfloat16 g_Blo[83886080];   // 160MB
__device__ __nv_bfloat16 g_Ahi[1245184];    // weights hi (max 256x4736)
__device__ __nv_bfloat16 g_Alo[1245184];
__device__ float g_offeat[4u * 64 * 128 * 128];
__device__ float g_om[4u * 216 * 128 * 128];
__device__ float g_fuse[4u * 128 * 128 * 128];
__device__ float g_up[4u * 128 * 128 * 128];

// ---------------------------------------------------------------------------
// im2col -> bf16 hi/lo planes, layout [n = b*HW + p][k = tap*Cp + ic]
// ---------------------------------------------------------------------------
__global__ void im2col_hilo(const float* __restrict__ s1, int c1, long bs1,
                            const float* __restrict__ s2, int c2, long bs2,
                            int H, int W, int Cp, int Kp,
                            uint32_t* __restrict__ Bh, uint32_t* __restrict__ Bl,
                            int total)
{
    int idx = blockIdx.x * blockDim.x + threadIdx.x;
    if (idx >= total) return;
    const int Kh = Kp >> 1;
    const int kk = idx % Kh;
    const int n  = idx / Kh;
    const int HW = H * W;
    const int b = n / HW, p = n % HW;
    const int y = p / W, x = p % W;
    const int k0 = kk * 2;
    const int t = k0 / Cp, c = k0 - t * Cp;
    const int Cin = c1 + c2;

    float v0 = 0.f, v1 = 0.f;
    if (t < 9) {
        const int yy = y + t / 3 - 1, xx = x + t % 3 - 1;
        if (yy >= 0 && yy < H && xx >= 0 && xx < W) {
            const long sp = (long)yy * W + xx;
            if (c < c1)            v0 = s1[(long)b * bs1 + (long)c * HW + sp];
            else if (c < Cin)      v0 = s2[(long)b * bs2 + (long)(c - c1) * HW + sp];
            const int c2i = c + 1;
            if (c2i < c1)          v1 = s1[(long)b * bs1 + (long)c2i * HW + sp];
            else if (c2i < Cin)    v1 = s2[(long)b * bs2 + (long)(c2i - c1) * HW + sp];
        }
    }
    __nv_bfloat16 h0 = __float2bfloat16(v0), h1 = __float2bfloat16(v1);
    __nv_bfloat16 l0 = __float2bfloat16(v0 - __bfloat162float(h0));
    __nv_bfloat16 l1 = __float2bfloat16(v1 - __bfloat162float(h1));
    __nv_bfloat162 hp = __nv_bfloat162(h0, h1), lp = __nv_bfloat162(l0, l1);
    const long o = (long)n * Kh + kk;
    Bh[o] = *(uint32_t*)&hp;
    Bl[o] = *(uint32_t*)&lp;
}

// ---------------------------------------------------------------------------
// Weight convert: fp32 w[M][Cin][9] -> bf16 hi/lo A[Mp][Kp], k = tap*Cp + ic
// ---------------------------------------------------------------------------
__global__ void wconv(const float* __restrict__ w, int M, int Cin, int Cp, int Kp,
                      uint32_t* __restrict__ Ah, uint32_t* __restrict__ Al, int total)
{
    int idx = blockIdx.x * blockDim.x + threadIdx.x;
    if (idx >= total) return;
    const int Kh = Kp >> 1;
    const int kk = idx % Kh;
    const int m  = idx / Kh;
    const int k0 = kk * 2;
    const int t = k0 / Cp, c = k0 - t * Cp;
    float v0 = 0.f, v1 = 0.f;
    if (m < M && t < 9) {
        if (c < Cin)     v0 = w[((long)m * Cin + c) * 9 + t];
        if (c + 1 < Cin) v1 = w[((long)m * Cin + c + 1) * 9 + t];
    }
    __nv_bfloat16 h0 = __float2bfloat16(v0), h1 = __float2bfloat16(v1);
    __nv_bfloat16 l0 = __float2bfloat16(v0 - __bfloat162float(h0));
    __nv_bfloat16 l1 = __float2bfloat16(v1 - __bfloat162float(h1));
    __nv_bfloat162 hp = __nv_bfloat162(h0, h1), lp = __nv_bfloat162(l0, l1);
    Ah[idx] = *(uint32_t*)&hp;
    Al[idx] = *(uint32_t*)&lp;
}

// ---------------------------------------------------------------------------
// mma.sync GEMM, bf16x3 hi/lo: D[128 M-tile, 128 N-tile], K-chunks of 32,
// cp.async double-buffered. A[Mp][Kp], B[Npix][Kp]. fp32 epilogue + bias.
// ---------------------------------------------------------------------------
#define LROW 40                       // smem row stride (bf16), conflict-free
#define PLANE (128 * LROW)            // 5120 bf16
#define GEMM_SMEM (2 * 4 * PLANE * 2) // 2 bufs * 4 planes * 5120 * 2B = 80KB

__global__ void __launch_bounds__(256)
gemm_mma(const __nv_bfloat16* __restrict__ Ahi, const __nv_bfloat16* __restrict__ Alo,
         const __nv_bfloat16* __restrict__ Bhi, const __nv_bfloat16* __restrict__ Blo,
         const float* __restrict__ bias, float* __restrict__ out,
         int Kp, int nchunks, int Cout, int ocStride, int HW)
{
    extern __shared__ __nv_bfloat16 sm[];

    const int tid = threadIdx.x, wid = tid >> 5, lane = tid & 31;
    const int g = lane >> 2, t = lane & 3;
    const int wm = wid >> 2, wn = wid & 3;     // 2x4 warp grid

    const int p0 = blockIdx.x * 128;
    const int m0 = blockIdx.y * 128;

    float acc[4][4][4];
#pragma unroll
    for (int i = 0; i < 4; i++)
#pragma unroll
        for (int j = 0; j < 4; j++)
#pragma unroll
            for (int k = 0; k < 4; k++) acc[i][j][k] = 0.f;

    // staging task geometry: 512 16B tasks per plane
    const int task0 = tid, task1 = tid + 256;
    const int r0 = task0 >> 2, s0 = task0 & 3;
    const int r1 = task1 >> 2, s1 = task1 & 3;
    const uint32_t smb = smem_u32(sm);

    auto stage = [&](int ci, int buf) {
        const long kc = (long)ci * 32;
        const uint32_t bufb = smb + (uint32_t)buf * 4 * PLANE * 2;
        // A hi/lo
        {
            const __nv_bfloat16* gA0 = Ahi + (long)(m0 + r0) * Kp + kc + s0 * 8;
            const __nv_bfloat16* gA1 = Ahi + (long)(m0 + r1) * Kp + kc + s1 * 8;
            CP16(bufb + r0 * 80 + s0 * 16, gA0);
            CP16(bufb + r1 * 80 + s1 * 16, gA1);
            const __nv_bfloat16* lA0 = Alo + (long)(m0 + r0) * Kp + kc + s0 * 8;
            const __nv_bfloat16* lA1 = Alo + (long)(m0 + r1) * Kp + kc + s1 * 8;
            CP16(bufb + PLANE * 2 + r0 * 80 + s0 * 16, lA0);
            CP16(bufb + PLANE * 2 + r1 * 80 + s1 * 16, lA1);
        }
        // B hi/lo
        {
            const __nv_bfloat16* gB0 = Bhi + (long)(p0 + r0) * Kp + kc + s0 * 8;
            const __nv_bfloat16* gB1 = Bhi + (long)(p0 + r1) * Kp + kc + s1 * 8;
            CP16(bufb + PLANE * 4 + r0 * 80 + s0 * 16, gB0);
            CP16(bufb + PLANE * 4 + r1 * 80 + s1 * 16, gB1);
            const __nv_bfloat16* lB0 = Blo + (long)(p0 + r0) * Kp + kc + s0 * 8;
            const __nv_bfloat16* lB1 = Blo + (long)(p0 + r1) * Kp + kc + s1 * 8;
            CP16(bufb + PLANE * 6 + r0 * 80 + s0 * 16, lB0);
            CP16(bufb + PLANE * 6 + r1 * 80 + s1 * 16, lB1);
        }
        CP_COMMIT();
    };

    stage(0, 0);

    for (int ci = 0; ci < nchunks; ci++) {
        const int buf = ci & 1;
        if (ci + 1 < nchunks) {
            stage(ci + 1, buf ^ 1);
            CP_WAIT(1);
        } else {
            CP_WAIT(0);
        }
        __syncthreads();

        const __nv_bfloat16* sAh = sm + (size_t)buf * 4 * PLANE;
        const __nv_bfloat16* sAl = sAh + PLANE;
        const __nv_bfloat16* sBh = sAh + 2 * PLANE;
        const __nv_bfloat16* sBl = sAh + 3 * PLANE;

#pragma unroll
        for (int s = 0; s < 2; s++) {
            const int cb = s * 16 + 2 * t;
            uint32_t afh[4][4], afl[4][4], bfh[4][2], bfl[4][2];
#pragma unroll
            for (int mt = 0; mt < 4; mt++) {
                const int row = wm * 64 + mt * 16 + g;
                afh[mt][0] = *(const uint32_t*)&sAh[row * LROW + cb];
                afh[mt][1] = *(const uint32_t*)&sAh[(row + 8) * LROW + cb];
                afh[mt][2] = *(const uint32_t*)&sAh[row * LROW + cb + 8];
                afh[mt][3] = *(const uint32_t*)&sAh[(row + 8) * LROW + cb + 8];
                afl[mt][0] = *(const uint32_t*)&sAl[row * LROW + cb];
                afl[mt][1] = *(const uint32_t*)&sAl[(row + 8) * LROW + cb];
                afl[mt][2] = *(const uint32_t*)&sAl[row * LROW + cb + 8];
                afl[mt][3] = *(const uint32_t*)&sAl[(row + 8) * LROW + cb + 8];
            }
#pragma unroll
            for (int nt = 0; nt < 4; nt++) {
                const int nrow = wn * 32 + nt * 8 + g;
                bfh[nt][0] = *(const uint32_t*)&sBh[nrow * LROW + cb];
                bfh[nt][1] = *(const uint32_t*)&sBh[nrow * LROW + cb + 8];
                bfl[nt][0] = *(const uint32_t*)&sBl[nrow * LROW + cb];
                bfl[nt][1] = *(const uint32_t*)&sBl[nrow * LROW + cb + 8];
            }
#pragma unroll
            for (int mt = 0; mt < 4; mt++)
#pragma unroll
                for (int nt = 0; nt < 4; nt++) {
                    mma16816(acc[mt][nt], afh[mt][0], afh[mt][1], afh[mt][2], afh[mt][3],
                             bfh[nt][0], bfh[nt][1]);
                    mma16816(acc[mt][nt], afh[mt][0], afh[mt][1], afh[mt][2], afh[mt][3],
                             bfl[nt][0], bfl[nt][1]);
                    mma16816(acc[mt][nt], afl[mt][0], afl[mt][1], afl[mt][2], afl[mt][3],
                             bfh[nt][0], bfh[nt][1]);
                }
        }
        __syncthreads();
    }

    // ---- epilogue ----
    const int bIdx = p0 / HW, prow0 = p0 % HW;
#pragma unroll
    for (int mt = 0; mt < 4; mt++) {
        const int oca = m0 + wm * 64 + mt * 16 + g;
        const int ocb = oca + 8;
        const float ba = (oca < Cout) ? bias[oca] : 0.f;
        const float bb = (ocb < Cout) ? bias[ocb] : 0.f;
#pragma unroll
        for (int nt = 0; nt < 4; nt++) {
            const int pc = prow0 + wn * 32 + nt * 8 + 2 * t;
            if (oca < Cout) {
                float2 v = make_float2(acc[mt][nt][0] + ba, acc[mt][nt][1] + ba);
                *(float2*)&out[((long)bIdx * ocStride + oca) * HW + pc] = v;
            }
            if (ocb < Cout) {
                float2 v = make_float2(acc[mt][nt][2] + bb, acc[mt][nt][3] + bb);
                *(float2*)&out[((long)bIdx * ocStride + ocb) * HW + pc] = v;
            }
        }
    }
}

// ---------------------------------------------------------------------------
// DCN bilinear sampler -> bf16 hi/lo B matrix [n][k = tap*C + g*Cg + c]
// ---------------------------------------------------------------------------
__global__ void dcn_sample_bf(const float* __restrict__ x, long xbs,
                              const float* __restrict__ om,
                              uint32_t* __restrict__ Bh, uint32_t* __restrict__ Bl,
                              int C, int H, int W, int total)
{
    int idx = blockIdx.x * blockDim.x + threadIdx.x;
    if (idx >= total) return;
    const int HW = H * W;
    const int p = idx % HW;
    const int k = (idx / HW) % 9;
    const int g = (idx / (HW * 9)) % 8;
    const int b = idx / (HW * 72);
    const int y = p / W, xq = p % W;

    const long omb = (long)b * 216 * HW + (long)(g * 9 + k) * HW + p;
    float dy = om[omb];
    float dx = om[omb + 72L * HW];
    float mk = om[omb + 144L * HW];
    mk = 1.f / (1.f + expf(-mk));

    float pyf = (float)y + (float)(k / 3 - 1) + dy;
    float pxf = (float)xq + (float)(k % 3 - 1) + dx;
    float y0f = floorf(pyf), x0f = floorf(pxf);
    int y0 = (int)y0f, x0i = (int)x0f;
    float ty = pyf - y0f, tx = pxf - x0f;
    int y1 = y0 + 1, x1i = x0i + 1;

    bool vy0 = (y0 >= 0) && (y0 < H), vy1 = (y1 >= 0) && (y1 < H);
    bool vx0 = (x0i >= 0) && (x0i < W), vx1 = (x1i >= 0) && (x1i < W);
    float w00 = (vy0 && vx0) ? (1.f - ty) * (1.f - tx) : 0.f;
    float w01 = (vy0 && vx1) ? (1.f - ty) * tx : 0.f;
    float w10 = (vy1 && vx0) ? ty * (1.f - tx) : 0.f;
    float w11 = (vy1 && vx1) ? ty * tx : 0.f;
    w00 *= mk; w01 *= mk; w10 *= mk; w11 *= mk;

    int cy0 = min(max(y0, 0), H - 1), cy1 = min(max(y1, 0), H - 1);
    int cx0 = min(max(x0i, 0), W - 1), cx1 = min(max(x1i, 0), W - 1);
    int i00 = cy0 * W + cx0, i01 = cy0 * W + cx1;
    int i10 = cy1 * W + cx0, i11 = cy1 * W + cx1;

    const int Cg = C >> 3;
    const int K = C * 9;
    const float* xb = x + (long)b * xbs + (long)g * Cg * HW;
    const long rowbase = ((long)b * HW + p) * K + (long)k * C + g * Cg;

    for (int c = 0; c < Cg; c += 2) {
        const float* xc0 = xb + (long)c * HW;
        const float* xc1 = xc0 + HW;
        float v0 = w00 * xc0[i00] + w01 * xc0[i01] + w10 * xc0[i10] + w11 * xc0[i11];
        float v1 = w00 * xc1[i00] + w01 * xc1[i01] + w10 * xc1[i10] + w11 * xc1[i11];
        __nv_bfloat16 h0 = __float2bfloat16(v0), h1 = __float2bfloat16(v1);
        __nv_bfloat16 l0 = __float2bfloat16(v0 - __bfloat162float(h0));
        __nv_bfloat16 l1 = __float2bfloat16(v1 - __bfloat162float(h1));
        __nv_bfloat162 hp = __nv_bfloat162(h0, h1), lp = __nv_bfloat162(l0, l1);
        const long o = (rowbase + c) >> 1;
        Bh[o] = *(uint32_t*)&hp;
        Bl[o] = *(uint32_t*)&lp;
    }
}

// ---------------------------------------------------------------------------
// Bilinear 2x upsample, align_corners=False (torch semantics)
// ---------------------------------------------------------------------------
__global__ void up2_kernel(const float* __restrict__ in, float* __restrict__ out,
                           int H, int W, int total)
{
    int idx = blockIdx.x * blockDim.x + threadIdx.x;
    if (idx >= total) return;
    const int W2 = 2 * W, H2 = 2 * H;
    const int ox = idx % W2;
    const int oy = (idx / W2) % H2;
    const int bc = idx / (W2 * H2);

    float sy = fmaxf(oy * 0.5f - 0.25f, 0.f);
    float sx = fmaxf(ox * 0.5f - 0.25f, 0.f);
    int y0 = (int)floorf(sy); float ty = sy - (float)y0; int y1 = min(y0 + 1, H - 1);
    int x0 = (int)floorf(sx); float tx = sx - (float)x0; int x1 = min(x0 + 1, W - 1);

    const float* p = in + (long)bc * H * W;
    float a = p[y0 * W + x0] * (1.f - ty) + p[y1 * W + x0] * ty;
    float c = p[y0 * W + x1] * (1.f - ty) + p[y1 * W + x1] * ty;
    out[idx] = a * (1.f - tx) + c * tx;
}

// ---------------------------------------------------------------------------
extern "C" void kernel_launch(void* const* d_in, const int* in_sizes, int n_in,
                              void* d_out, int out_size)
{
    const float *x0 = nullptr, *x1 = nullptr, *x2 = nullptr;
    const float *flow0 = nullptr, *flow1 = nullptr, *flow2 = nullptr;
    for (int i = 0; i < 6; i++) {
        const float* p = (const float*)d_in[i];
        switch (in_sizes[i]) {
            case 4 * 2 * 64 * 128 * 128: x0 = p; break;
            case 4 * 2 * 128 * 64 * 64:  x1 = p; break;
            case 4 * 2 * 256 * 32 * 32:  x2 = p; break;
            case 4 * 2 * 128 * 128:      flow0 = p; break;
            case 4 * 2 * 64 * 64:        flow1 = p; break;
            case 4 * 2 * 32 * 32:        flow2 = p; break;
        }
    }
    const float* off_w0 = (const float*)d_in[6];  const float* off_b0 = (const float*)d_in[7];
    const float* co_w0  = (const float*)d_in[8];  const float* co_b0  = (const float*)d_in[9];
    const float* dcn_w0 = (const float*)d_in[10]; const float* dcn_b0 = (const float*)d_in[11];
    const float* off_w1 = (const float*)d_in[12]; const float* off_b1 = (const float*)d_in[13];
    const float* co_w1  = (const float*)d_in[14]; const float* co_b1  = (const float*)d_in[15];
    const float* dcn_w1 = (const float*)d_in[16]; const float* dcn_b1 = (const float*)d_in[17];
    const float* off_w2 = (const float*)d_in[18]; const float* off_b2 = (const float*)d_in[19];
    const float* co_w2  = (const float*)d_in[20]; const float* co_b2  = (const float*)d_in[21];
    const float* dcn_w2 = (const float*)d_in[22]; const float* dcn_b2 = (const float*)d_in[23];
    const float* ch_w0  = (const float*)d_in[24]; const float* ch_b0  = (const float*)d_in[25];
    const float* ft_w0  = (const float*)d_in[26]; const float* ft_b0  = (const float*)d_in[27];
    const float* ch_w1  = (const float*)d_in[28]; const float* ch_b1  = (const float*)d_in[29];
    const float* ft_w1  = (const float*)d_in[30]; const float* ft_b1  = (const float*)d_in[31];

    __nv_bfloat16 *Bhi, *Blo, *Ahi, *Alo;
    float *offeat, *om, *fuse, *up;
    cudaGetSymbolAddress((void**)&Bhi, g_Bhi);
    cudaGetSymbolAddress((void**)&Blo, g_Blo);
    cudaGetSymbolAddress((void**)&Ahi, g_Ahi);
    cudaGetSymbolAddress((void**)&Alo, g_Alo);
    cudaGetSymbolAddress((void**)&offeat, g_offeat);
    cudaGetSymbolAddress((void**)&om, g_om);
    cudaGetSymbolAddress((void**)&fuse, g_fuse);
    cudaGetSymbolAddress((void**)&up, g_up);

    cudaFuncSetAttribute(gemm_mma, cudaFuncAttributeMaxDynamicSharedMemorySize, GEMM_SMEM);

    float* out0 = (float*)d_out;                    // (4,64,128,128)
    float* out1 = out0 + 4L * 64 * 128 * 128;       // (4,128,64,64)
    float* out2 = out1 + 4L * 128 * 64 * 64;        // (4,256,32,32)

    const int B = 4;

    auto IM2COL = [&](const float* s1, int c1, long bs1, const float* s2, int c2, long bs2,
                      int H, int W, int Cp, int Kp) {
        int total = B * H * W * (Kp >> 1);
        im2col_hilo<<<(total + 255) / 256, 256>>>(s1, c1, bs1, s2, c2, bs2, H, W, Cp, Kp,
                                                  (uint32_t*)Bhi, (uint32_t*)Blo, total);
    };
    auto WCONV = [&](const float* w, int M, int Cin, int Cp, int Kp, int Mp) {
        int total = Mp * (Kp >> 1);
        wconv<<<(total + 255) / 256, 256>>>(w, M, Cin, Cp, Kp,
                                            (uint32_t*)Ahi, (uint32_t*)Alo, total);
    };
    auto GEMM = [&](const float* bias, float* out, int Kp, int Cout, int ocStride,
                    int HW, int Mtiles) {
        dim3 grid((B * HW) / 128, Mtiles);
        gemm_mma<<<grid, 256, GEMM_SMEM>>>(Ahi, Alo, Bhi, Blo, bias, out,
                                           Kp, Kp / 32, Cout, ocStride, HW);
    };

    // ================= level 2: C=256, 32x32 =================
    {
        const int H = 32, W = 32, HW = H * W;
        IM2COL(x2, 512, 512L * HW, flow2, 2, 2L * HW, H, W, 520, 4736);
        WCONV(off_w2, 256, 514, 520, 4736, 256);
        GEMM(off_b2, offeat, 4736, 256, 256, HW, 2);

        IM2COL(offeat, 256, 256L * HW, nullptr, 0, 0, H, W, 256, 2304);
        WCONV(co_w2, 216, 256, 256, 2304, 256);
        GEMM(co_b2, om, 2304, 216, 216, HW, 2);

        int st = B * 72 * HW;
        dcn_sample_bf<<<(st + 255) / 256, 256>>>(x2 + 256L * HW, 512L * HW, om,
                                                 (uint32_t*)Bhi, (uint32_t*)Blo,
                                                 256, H, W, st);
        WCONV(dcn_w2, 256, 256, 256, 2304, 256);
        GEMM(dcn_b2, out2, 2304, 256, 256, HW, 2);

        int ut = B * 256 * 4 * HW;
        up2_kernel<<<(ut + 255) / 256, 256>>>(out2, up, H, W, ut);
    }

    // ================= level 1: C=128, 64x64 =================
    {
        const int H = 64, W = 64, HW = H * W;
        IM2COL(x1, 256, 256L * HW, flow1, 2, 2L * HW, H, W, 264, 2432);
        WCONV(off_w1, 128, 258, 264, 2432, 128);
        GEMM(off_b1, offeat, 2432, 128, 128, HW, 1);

        IM2COL(offeat, 128, 128L * HW, nullptr, 0, 0, H, W, 128, 1152);
        WCONV(co_w1, 216, 128, 128, 1152, 256);
        GEMM(co_b1, om, 1152, 216, 216, HW, 2);

        int st = B * 72 * HW;
        dcn_sample_bf<<<(st + 255) / 256, 256>>>(x1 + 128L * HW, 256L * HW, om,
                                                 (uint32_t*)Bhi, (uint32_t*)Blo,
                                                 128, H, W, st);
        WCONV(dcn_w1, 128, 128, 128, 1152, 128);
        GEMM(dcn_b1, fuse, 1152, 128, 256, HW, 1);            // fuse ch [0,128)

        IM2COL(up, 256, 256L * HW, nullptr, 0, 0, H, W, 256, 2304);
        WCONV(ch_w1, 128, 256, 256, 2304, 128);
        GEMM(ch_b1, fuse + 128L * HW, 2304, 128, 256, HW, 1); // fuse ch [128,256)

        IM2COL(fuse, 256, 256L * HW, nullptr, 0, 0, H, W, 256, 2304);
        WCONV(ft_w1, 128, 256, 256, 2304, 128);
        GEMM(ft_b1, out1, 2304, 128, 128, HW, 1);

        int ut = B * 128 * 4 * HW;
        up2_kernel<<<(ut + 255) / 256, 256>>>(out1, up, H, W, ut);
    }

    // ================= level 0: C=64, 128x128 =================
    {
        const int H = 128, W = 128, HW = H * W;
        IM2COL(x0, 128, 128L * HW, flow0, 2, 2L * HW, H, W, 136, 1280);
        WCONV(off_w0, 64, 130, 136, 1280, 128);
        GEMM(off_b0, offeat, 1280, 64, 64, HW, 1);

        IM2COL(offeat, 64, 64L * HW, nullptr, 0, 0, H, W, 64, 576);
        WCONV(co_w0, 216, 64, 64, 576, 256);
        GEMM(co_b0, om, 576, 216, 216, HW, 2);

        int st = B * 72 * HW;
        dcn_sample_bf<<<(st + 255) / 256, 256>>>(x0 + 64L * HW, 128L * HW, om,
                                                 (uint32_t*)Bhi, (uint32_t*)Blo,
                                                 64, H, W, st);
        WCONV(dcn_w0, 64, 64, 64, 576, 128);
        GEMM(dcn_b0, fuse, 576, 64, 128, HW, 1);              // fuse ch [0,64)

        IM2COL(up, 128, 128L * HW, nullptr, 0, 0, H, W, 128, 1152);
        WCONV(ch_w0, 64, 128, 128, 1152, 128);
        GEMM(ch_b0, fuse + 64L * HW, 1152, 64, 128, HW, 1);   // fuse ch [64,128)

        IM2COL(fuse, 128, 128L * HW, nullptr, 0, 0, H, W, 128, 1152);
        WCONV(ft_w0, 64, 128, 128, 1152, 128);
        GEMM(ft_b0, out0, 1152, 64, 64, HW, 1);
    }
}

// round 7
// speedup vs baseline: 2.6540x; 1.3391x over previous
#include <cuda_runtime.h>
#include <cuda_bf16.h>
#include <math.h>
#include <stdint.h>

// ===========================================================================
// MotionCompensationBlock — mma.sync (HMMA bf16x3 hi/lo) implicit-GEMM
// Round 7: coalesced im2col (smem transpose) + vectorized DCN sampler stores
// ===========================================================================

__device__ __forceinline__ uint32_t smem_u32(const void* p) {
    uint32_t a;
    asm("{ .reg .u64 t; cvta.to.shared.u64 t, %1; cvt.u32.u64 %0, t; }" : "=r"(a) : "l"(p));
    return a;
}

#define CP16(dst, src) \
    asm volatile("cp.async.cg.shared.global [%0], [%1], 16;" :: "r"(dst), "l"(src) : "memory")
#define CP_COMMIT() asm volatile("cp.async.commit_group;" ::: "memory")
#define CP_WAIT(n)  asm volatile("cp.async.wait_group %0;" :: "n"(n) : "memory")

__device__ __forceinline__ void mma16816(float* c, uint32_t a0, uint32_t a1,
                                         uint32_t a2, uint32_t a3,
                                         uint32_t b0, uint32_t b1) {
    asm volatile(
        "mma.sync.aligned.m16n8k16.row.col.f32.bf16.bf16.f32 "
        "{%0,%1,%2,%3}, {%4,%5,%6,%7}, {%8,%9}, {%0,%1,%2,%3};"
        : "+f"(c[0]), "+f"(c[1]), "+f"(c[2]), "+f"(c[3])
        : "r"(a0), "r"(a1), "r"(a2), "r"(a3), "r"(b0), "r"(b1));
}

__device__ __forceinline__ uint32_t hilo_pack_hi(float v0, float v1,
                                                 uint32_t& lo) {
    __nv_bfloat16 h0 = __float2bfloat16(v0), h1 = __float2bfloat16(v1);
    __nv_bfloat16 l0 = __float2bfloat16(v0 - __bfloat162float(h0));
    __nv_bfloat16 l1 = __float2bfloat16(v1 - __bfloat162float(h1));
    __nv_bfloat162 hp = __nv_bfloat162(h0, h1), lp = __nv_bfloat162(l0, l1);
    lo = *(uint32_t*)&lp;
    return *(uint32_t*)&hp;
}

// ------------------------------ scratch -----------------------------------
__device__ __nv_bfloat16 g_Bhi[83886080];
__device__ __nv_bfloat16 g_Blo[83886080];
__device__ __nv_bfloat16 g_Ahi[1245184];
__device__ __nv_bfloat16 g_Alo[1245184];
__device__ float g_offeat[4u * 64 * 128 * 128];
__device__ float g_om[4u * 216 * 128 * 128];
__device__ float g_fuse[4u * 128 * 128 * 128];
__device__ float g_up[4u * 128 * 128 * 128];

// ---------------------------------------------------------------------------
// im2col v2: coalesced both sides via smem transpose. Tile: 32 k-pairs x 64
// pixels. Phase 1 reads with threads along pixels; phase 2 writes with
// threads along k. Output layout [n][k], k = tap*Cp + ic, hi/lo planes.
// ---------------------------------------------------------------------------
__global__ void __launch_bounds__(256)
im2col_v2(const float* __restrict__ s1, int c1, long bs1,
          const float* __restrict__ s2, int c2, long bs2,
          int H, int W, int Cp, int Kh /* = Kp/2 */,
          uint32_t* __restrict__ Bh, uint32_t* __restrict__ Bl)
{
    __shared__ uint32_t sh[32][65];
    __shared__ uint32_t sl[32][65];
    __shared__ int st_t[32], st_c[32];
    __shared__ int sp_b[64], sp_y[64], sp_x[64];

    const int tid = threadIdx.x;
    const int kk0 = blockIdx.x * 32;
    const long n0 = (long)blockIdx.y * 64;
    const int HW = H * W;

    if (tid < 32) {
        int k0 = (kk0 + tid) * 2;
        int t = k0 / Cp;
        st_t[tid] = t;
        st_c[tid] = k0 - t * Cp;
    } else if (tid < 96) {
        int i = tid - 32;
        long n = n0 + i;
        int b = (int)(n / HW);
        int p = (int)(n - (long)b * HW);
        sp_b[i] = b;
        sp_y[i] = p / W;
        sp_x[i] = p % W;
    }
    __syncthreads();

    const int Cin = c1 + c2;
#pragma unroll
    for (int e = tid; e < 2048; e += 256) {
        const int p = e & 63, kk = e >> 6;
        const int t = st_t[kk], c = st_c[kk];
        float v0 = 0.f, v1 = 0.f;
        if (t < 9) {
            const int yy = sp_y[p] + t / 3 - 1;
            const int xx = sp_x[p] + t % 3 - 1;
            if (yy >= 0 && yy < H && xx >= 0 && xx < W) {
                const long sp = (long)yy * W + xx;
                const int b = sp_b[p];
                if (c < c1)          v0 = s1[(long)b * bs1 + (long)c * HW + sp];
                else if (c < Cin)    v0 = s2[(long)b * bs2 + (long)(c - c1) * HW + sp];
                const int cc = c + 1;
                if (cc < c1)         v1 = s1[(long)b * bs1 + (long)cc * HW + sp];
                else if (cc < Cin)   v1 = s2[(long)b * bs2 + (long)(cc - c1) * HW + sp];
            }
        }
        uint32_t lo;
        uint32_t hi = hilo_pack_hi(v0, v1, lo);
        sh[kk][p] = hi;
        sl[kk][p] = lo;
    }
    __syncthreads();

#pragma unroll
    for (int e = tid; e < 2048; e += 256) {
        const int kk = e & 31, p = e >> 5;
        const long o = (n0 + p) * Kh + kk0 + kk;
        Bh[o] = sh[kk][p];
        Bl[o] = sl[kk][p];
    }
}

// ---------------------------------------------------------------------------
// Weight convert: fp32 w[M][Cin][9] -> bf16 hi/lo A[Mp][Kp], k = tap*Cp + ic
// ---------------------------------------------------------------------------
__global__ void wconv(const float* __restrict__ w, int M, int Cin, int Cp, int Kp,
                      uint32_t* __restrict__ Ah, uint32_t* __restrict__ Al, int total)
{
    int idx = blockIdx.x * blockDim.x + threadIdx.x;
    if (idx >= total) return;
    const int Kh = Kp >> 1;
    const int kk = idx % Kh;
    const int m  = idx / Kh;
    const int k0 = kk * 2;
    const int t = k0 / Cp, c = k0 - t * Cp;
    float v0 = 0.f, v1 = 0.f;
    if (m < M && t < 9) {
        if (c < Cin)     v0 = w[((long)m * Cin + c) * 9 + t];
        if (c + 1 < Cin) v1 = w[((long)m * Cin + c + 1) * 9 + t];
    }
    uint32_t lo;
    uint32_t hi = hilo_pack_hi(v0, v1, lo);
    Ah[idx] = hi;
    Al[idx] = lo;
}

// ---------------------------------------------------------------------------
// mma.sync GEMM, bf16x3 hi/lo: D[128 M-tile, 128 N-tile], K-chunks of 32,
// cp.async double-buffered.
// ---------------------------------------------------------------------------
#define LROW 40
#define PLANE (128 * LROW)
#define GEMM_SMEM (2 * 4 * PLANE * 2)

__global__ void __launch_bounds__(256)
gemm_mma(const __nv_bfloat16* __restrict__ Ahi, const __nv_bfloat16* __restrict__ Alo,
         const __nv_bfloat16* __restrict__ Bhi, const __nv_bfloat16* __restrict__ Blo,
         const float* __restrict__ bias, float* __restrict__ out,
         int Kp, int nchunks, int Cout, int ocStride, int HW)
{
    extern __shared__ __nv_bfloat16 sm[];

    const int tid = threadIdx.x, wid = tid >> 5, lane = tid & 31;
    const int g = lane >> 2, t = lane & 3;
    const int wm = wid >> 2, wn = wid & 3;

    const int p0 = blockIdx.x * 128;
    const int m0 = blockIdx.y * 128;

    float acc[4][4][4];
#pragma unroll
    for (int i = 0; i < 4; i++)
#pragma unroll
        for (int j = 0; j < 4; j++)
#pragma unroll
            for (int k = 0; k < 4; k++) acc[i][j][k] = 0.f;

    const int task0 = tid, task1 = tid + 256;
    const int r0 = task0 >> 2, s0 = task0 & 3;
    const int r1 = task1 >> 2, s1 = task1 & 3;
    const uint32_t smb = smem_u32(sm);

    auto stage = [&](int ci, int buf) {
        const long kc = (long)ci * 32;
        const uint32_t bufb = smb + (uint32_t)buf * 4 * PLANE * 2;
        {
            const __nv_bfloat16* gA0 = Ahi + (long)(m0 + r0) * Kp + kc + s0 * 8;
            const __nv_bfloat16* gA1 = Ahi + (long)(m0 + r1) * Kp + kc + s1 * 8;
            CP16(bufb + r0 * 80 + s0 * 16, gA0);
            CP16(bufb + r1 * 80 + s1 * 16, gA1);
            const __nv_bfloat16* lA0 = Alo + (long)(m0 + r0) * Kp + kc + s0 * 8;
            const __nv_bfloat16* lA1 = Alo + (long)(m0 + r1) * Kp + kc + s1 * 8;
            CP16(bufb + PLANE * 2 + r0 * 80 + s0 * 16, lA0);
            CP16(bufb + PLANE * 2 + r1 * 80 + s1 * 16, lA1);
        }
        {
            const __nv_bfloat16* gB0 = Bhi + (long)(p0 + r0) * Kp + kc + s0 * 8;
            const __nv_bfloat16* gB1 = Bhi + (long)(p0 + r1) * Kp + kc + s1 * 8;
            CP16(bufb + PLANE * 4 + r0 * 80 + s0 * 16, gB0);
            CP16(bufb + PLANE * 4 + r1 * 80 + s1 * 16, gB1);
            const __nv_bfloat16* lB0 = Blo + (long)(p0 + r0) * Kp + kc + s0 * 8;
            const __nv_bfloat16* lB1 = Blo + (long)(p0 + r1) * Kp + kc + s1 * 8;
            CP16(bufb + PLANE * 6 + r0 * 80 + s0 * 16, lB0);
            CP16(bufb + PLANE * 6 + r1 * 80 + s1 * 16, lB1);
        }
        CP_COMMIT();
    };

    stage(0, 0);

    for (int ci = 0; ci < nchunks; ci++) {
        const int buf = ci & 1;
        if (ci + 1 < nchunks) {
            stage(ci + 1, buf ^ 1);
            CP_WAIT(1);
        } else {
            CP_WAIT(0);
        }
        __syncthreads();

        const __nv_bfloat16* sAh = sm + (size_t)buf * 4 * PLANE;
        const __nv_bfloat16* sAl = sAh + PLANE;
        const __nv_bfloat16* sBh = sAh + 2 * PLANE;
        const __nv_bfloat16* sBl = sAh + 3 * PLANE;

#pragma unroll
        for (int s = 0; s < 2; s++) {
            const int cb = s * 16 + 2 * t;
            uint32_t afh[4][4], afl[4][4], bfh[4][2], bfl[4][2];
#pragma unroll
            for (int mt = 0; mt < 4; mt++) {
                const int row = wm * 64 + mt * 16 + g;
                afh[mt][0] = *(const uint32_t*)&sAh[row * LROW + cb];
                afh[mt][1] = *(const uint32_t*)&sAh[(row + 8) * LROW + cb];
                afh[mt][2] = *(const uint32_t*)&sAh[row * LROW + cb + 8];
                afh[mt][3] = *(const uint32_t*)&sAh[(row + 8) * LROW + cb + 8];
                afl[mt][0] = *(const uint32_t*)&sAl[row * LROW + cb];
                afl[mt][1] = *(const uint32_t*)&sAl[(row + 8) * LROW + cb];
                afl[mt][2] = *(const uint32_t*)&sAl[row * LROW + cb + 8];
                afl[mt][3] = *(const uint32_t*)&sAl[(row + 8) * LROW + cb + 8];
            }
#pragma unroll
            for (int nt = 0; nt < 4; nt++) {
                const int nrow = wn * 32 + nt * 8 + g;
                bfh[nt][0] = *(const uint32_t*)&sBh[nrow * LROW + cb];
                bfh[nt][1] = *(const uint32_t*)&sBh[nrow * LROW + cb + 8];
                bfl[nt][0] = *(const uint32_t*)&sBl[nrow * LROW + cb];
                bfl[nt][1] = *(const uint32_t*)&sBl[nrow * LROW + cb + 8];
            }
#pragma unroll
            for (int mt = 0; mt < 4; mt++)
#pragma unroll
                for (int nt = 0; nt < 4; nt++) {
                    mma16816(acc[mt][nt], afh[mt][0], afh[mt][1], afh[mt][2], afh[mt][3],
                             bfh[nt][0], bfh[nt][1]);
                    mma16816(acc[mt][nt], afh[mt][0], afh[mt][1], afh[mt][2], afh[mt][3],
                             bfl[nt][0], bfl[nt][1]);
                    mma16816(acc[mt][nt], afl[mt][0], afl[mt][1], afl[mt][2], afl[mt][3],
                             bfh[nt][0], bfh[nt][1]);
                }
        }
        __syncthreads();
    }

    const int bIdx = p0 / HW, prow0 = p0 % HW;
#pragma unroll
    for (int mt = 0; mt < 4; mt++) {
        const int oca = m0 + wm * 64 + mt * 16 + g;
        const int ocb = oca + 8;
        const float ba = (oca < Cout) ? bias[oca] : 0.f;
        const float bb = (ocb < Cout) ? bias[ocb] : 0.f;
#pragma unroll
        for (int nt = 0; nt < 4; nt++) {
            const int pc = prow0 + wn * 32 + nt * 8 + 2 * t;
            if (oca < Cout) {
                float2 v = make_float2(acc[mt][nt][0] + ba, acc[mt][nt][1] + ba);
                *(float2*)&out[((long)bIdx * ocStride + oca) * HW + pc] = v;
            }
            if (ocb < Cout) {
                float2 v = make_float2(acc[mt][nt][2] + bb, acc[mt][nt][3] + bb);
                *(float2*)&out[((long)bIdx * ocStride + ocb) * HW + pc] = v;
            }
        }
    }
}

// ---------------------------------------------------------------------------
// DCN bilinear sampler -> bf16 hi/lo B matrix [n][k = tap*C + g*Cg + c].
// Vectorized uint4 stores (8 channels per store; rowbase 8-aligned).
// ---------------------------------------------------------------------------
__global__ void dcn_sample_bf(const float* __restrict__ x, long xbs,
                              const float* __restrict__ om,
                              uint4* __restrict__ Bh4, uint4* __restrict__ Bl4,
                              int C, int H, int W, int total)
{
    int idx = blockIdx.x * blockDim.x + threadIdx.x;
    if (idx >= total) return;
    const int HW = H * W;
    const int p = idx % HW;
    const int k = (idx / HW) % 9;
    const int g = (idx / (HW * 9)) % 8;
    const int b = idx / (HW * 72);
    const int y = p / W, xq = p % W;

    const long omb = (long)b * 216 * HW + (long)(g * 9 + k) * HW + p;
    float dy = om[omb];
    float dx = om[omb + 72L * HW];
    float mk = om[omb + 144L * HW];
    mk = 1.f / (1.f + expf(-mk));

    float pyf = (float)y + (float)(k / 3 - 1) + dy;
    float pxf = (float)xq + (float)(k % 3 - 1) + dx;
    float y0f = floorf(pyf), x0f = floorf(pxf);
    int y0 = (int)y0f, x0i = (int)x0f;
    float ty = pyf - y0f, tx = pxf - x0f;
    int y1 = y0 + 1, x1i = x0i + 1;

    bool vy0 = (y0 >= 0) && (y0 < H), vy1 = (y1 >= 0) && (y1 < H);
    bool vx0 = (x0i >= 0) && (x0i < W), vx1 = (x1i >= 0) && (x1i < W);
    float w00 = (vy0 && vx0) ? (1.f - ty) * (1.f - tx) : 0.f;
    float w01 = (vy0 && vx1) ? (1.f - ty) * tx : 0.f;
    float w10 = (vy1 && vx0) ? ty * (1.f - tx) : 0.f;
    float w11 = (vy1 && vx1) ? ty * tx : 0.f;
    w00 *= mk; w01 *= mk; w10 *= mk; w11 *= mk;

    int cy0 = min(max(y0, 0), H - 1), cy1 = min(max(y1, 0), H - 1);
    int cx0 = min(max(x0i, 0), W - 1), cx1 = min(max(x1i, 0), W - 1);
    int i00 = cy0 * W + cx0, i01 = cy0 * W + cx1;
    int i10 = cy1 * W + cx0, i11 = cy1 * W + cx1;

    const int Cg = C >> 3;
    const int K = C * 9;
    const float* xb = x + (long)b * xbs + (long)g * Cg * HW;
    const long rowbase = ((long)b * HW + p) * K + (long)k * C + (long)g * Cg;
    const long o4 = rowbase >> 3;   // uint4 index (rowbase multiple of 8)

    for (int cb = 0; cb < Cg; cb += 8) {
        uint32_t hv[4], lv[4];
#pragma unroll
        for (int j = 0; j < 4; j++) {
            const float* xc0 = xb + (long)(cb + 2 * j) * HW;
            const float* xc1 = xc0 + HW;
            float v0 = w00 * xc0[i00] + w01 * xc0[i01] + w10 * xc0[i10] + w11 * xc0[i11];
            float v1 = w00 * xc1[i00] + w01 * xc1[i01] + w10 * xc1[i10] + w11 * xc1[i11];
            hv[j] = hilo_pack_hi(v0, v1, lv[j]);
        }
        const long o = o4 + (cb >> 3);
        Bh4[o] = make_uint4(hv[0], hv[1], hv[2], hv[3]);
        Bl4[o] = make_uint4(lv[0], lv[1], lv[2], lv[3]);
    }
}

// ---------------------------------------------------------------------------
// Bilinear 2x upsample, align_corners=False
// ---------------------------------------------------------------------------
__global__ void up2_kernel(const float* __restrict__ in, float* __restrict__ out,
                           int H, int W, int total)
{
    int idx = blockIdx.x * blockDim.x + threadIdx.x;
    if (idx >= total) return;
    const int W2 = 2 * W, H2 = 2 * H;
    const int ox = idx % W2;
    const int oy = (idx / W2) % H2;
    const int bc = idx / (W2 * H2);

    float sy = fmaxf(oy * 0.5f - 0.25f, 0.f);
    float sx = fmaxf(ox * 0.5f - 0.25f, 0.f);
    int y0 = (int)floorf(sy); float ty = sy - (float)y0; int y1 = min(y0 + 1, H - 1);
    int x0 = (int)floorf(sx); float tx = sx - (float)x0; int x1 = min(x0 + 1, W - 1);

    const float* p = in + (long)bc * H * W;
    float a = p[y0 * W + x0] * (1.f - ty) + p[y1 * W + x0] * ty;
    float c = p[y0 * W + x1] * (1.f - ty) + p[y1 * W + x1] * ty;
    out[idx] = a * (1.f - tx) + c * tx;
}

// ---------------------------------------------------------------------------
extern "C" void kernel_launch(void* const* d_in, const int* in_sizes, int n_in,
                              void* d_out, int out_size)
{
    const float *x0 = nullptr, *x1 = nullptr, *x2 = nullptr;
    const float *flow0 = nullptr, *flow1 = nullptr, *flow2 = nullptr;
    for (int i = 0; i < 6; i++) {
        const float* p = (const float*)d_in[i];
        switch (in_sizes[i]) {
            case 4 * 2 * 64 * 128 * 128: x0 = p; break;
            case 4 * 2 * 128 * 64 * 64:  x1 = p; break;
            case 4 * 2 * 256 * 32 * 32:  x2 = p; break;
            case 4 * 2 * 128 * 128:      flow0 = p; break;
            case 4 * 2 * 64 * 64:        flow1 = p; break;
            case 4 * 2 * 32 * 32:        flow2 = p; break;
        }
    }
    const float* off_w0 = (const float*)d_in[6];  const float* off_b0 = (const float*)d_in[7];
    const float* co_w0  = (const float*)d_in[8];  const float* co_b0  = (const float*)d_in[9];
    const float* dcn_w0 = (const float*)d_in[10]; const float* dcn_b0 = (const float*)d_in[11];
    const float* off_w1 = (const float*)d_in[12]; const float* off_b1 = (const float*)d_in[13];
    const float* co_w1  = (const float*)d_in[14]; const float* co_b1  = (const float*)d_in[15];
    const float* dcn_w1 = (const float*)d_in[16]; const float* dcn_b1 = (const float*)d_in[17];
    const float* off_w2 = (const float*)d_in[18]; const float* off_b2 = (const float*)d_in[19];
    const float* co_w2  = (const float*)d_in[20]; const float* co_b2  = (const float*)d_in[21];
    const float* dcn_w2 = (const float*)d_in[22]; const float* dcn_b2 = (const float*)d_in[23];
    const float* ch_w0  = (const float*)d_in[24]; const float* ch_b0  = (const float*)d_in[25];
    const float* ft_w0  = (const float*)d_in[26]; const float* ft_b0  = (const float*)d_in[27];
    const float* ch_w1  = (const float*)d_in[28]; const float* ch_b1  = (const float*)d_in[29];
    const float* ft_w1  = (const float*)d_in[30]; const float* ft_b1  = (const float*)d_in[31];

    __nv_bfloat16 *Bhi, *Blo, *Ahi, *Alo;
    float *offeat, *om, *fuse, *up;
    cudaGetSymbolAddress((void**)&Bhi, g_Bhi);
    cudaGetSymbolAddress((void**)&Blo, g_Blo);
    cudaGetSymbolAddress((void**)&Ahi, g_Ahi);
    cudaGetSymbolAddress((void**)&Alo, g_Alo);
    cudaGetSymbolAddress((void**)&offeat, g_offeat);
    cudaGetSymbolAddress((void**)&om, g_om);
    cudaGetSymbolAddress((void**)&fuse, g_fuse);
    cudaGetSymbolAddress((void**)&up, g_up);

    cudaFuncSetAttribute(gemm_mma, cudaFuncAttributeMaxDynamicSharedMemorySize, GEMM_SMEM);

    float* out0 = (float*)d_out;
    float* out1 = out0 + 4L * 64 * 128 * 128;
    float* out2 = out1 + 4L * 128 * 64 * 64;

    const int B = 4;

    auto IM2COL = [&](const float* s1, int c1, long bs1, const float* s2, int c2, long bs2,
                      int H, int W, int Cp, int Kp) {
        const int Kh = Kp >> 1;
        dim3 grid(Kh / 32, (B * H * W) / 64);
        im2col_v2<<<grid, 256>>>(s1, c1, bs1, s2, c2, bs2, H, W, Cp, Kh,
                                 (uint32_t*)Bhi, (uint32_t*)Blo);
    };
    auto WCONV = [&](const float* w, int M, int Cin, int Cp, int Kp, int Mp) {
        int total = Mp * (Kp >> 1);
        wconv<<<(total + 255) / 256, 256>>>(w, M, Cin, Cp, Kp,
                                            (uint32_t*)Ahi, (uint32_t*)Alo, total);
    };
    auto GEMM = [&](const float* bias, float* out, int Kp, int Cout, int ocStride,
                    int HW, int Mtiles) {
        dim3 grid((B * HW) / 128, Mtiles);
        gemm_mma<<<grid, 256, GEMM_SMEM>>>(Ahi, Alo, Bhi, Blo, bias, out,
                                           Kp, Kp / 32, Cout, ocStride, HW);
    };

    // ================= level 2: C=256, 32x32 =================
    {
        const int H = 32, W = 32, HW = H * W;
        IM2COL(x2, 512, 512L * HW, flow2, 2, 2L * HW, H, W, 520, 4736);
        WCONV(off_w2, 256, 514, 520, 4736, 256);
        GEMM(off_b2, offeat, 4736, 256, 256, HW, 2);

        IM2COL(offeat, 256, 256L * HW, nullptr, 0, 0, H, W, 256, 2304);
        WCONV(co_w2, 216, 256, 256, 2304, 256);
        GEMM(co_b2, om, 2304, 216, 216, HW, 2);

        int st = B * 72 * HW;
        dcn_sample_bf<<<(st + 255) / 256, 256>>>(x2 + 256L * HW, 512L * HW, om,
                                                 (uint4*)Bhi, (uint4*)Blo,
                                                 256, H, W, st);
        WCONV(dcn_w2, 256, 256, 256, 2304, 256);
        GEMM(dcn_b2, out2, 2304, 256, 256, HW, 2);

        int ut = B * 256 * 4 * HW;
        up2_kernel<<<(ut + 255) / 256, 256>>>(out2, up, H, W, ut);
    }

    // ================= level 1: C=128, 64x64 =================
    {
        const int H = 64, W = 64, HW = H * W;
        IM2COL(x1, 256, 256L * HW, flow1, 2, 2L * HW, H, W, 264, 2432);
        WCONV(off_w1, 128, 258, 264, 2432, 128);
        GEMM(off_b1, offeat, 2432, 128, 128, HW, 1);

        IM2COL(offeat, 128, 128L * HW, nullptr, 0, 0, H, W, 128, 1152);
        WCONV(co_w1, 216, 128, 128, 1152, 256);
        GEMM(co_b1, om, 1152, 216, 216, HW, 2);

        int st = B * 72 * HW;
        dcn_sample_bf<<<(st + 255) / 256, 256>>>(x1 + 128L * HW, 256L * HW, om,
                                                 (uint4*)Bhi, (uint4*)Blo,
                                                 128, H, W, st);
        WCONV(dcn_w1, 128, 128, 128, 1152, 128);
        GEMM(dcn_b1, fuse, 1152, 128, 256, HW, 1);

        IM2COL(up, 256, 256L * HW, nullptr, 0, 0, H, W, 256, 2304);
        WCONV(ch_w1, 128, 256, 256, 2304, 128);
        GEMM(ch_b1, fuse + 128L * HW, 2304, 128, 256, HW, 1);

        IM2COL(fuse, 256, 256L * HW, nullptr, 0, 0, H, W, 256, 2304);
        WCONV(ft_w1, 128, 256, 256, 2304, 128);
        GEMM(ft_b1, out1, 2304, 128, 128, HW, 1);

        int ut = B * 128 * 4 * HW;
        up2_kernel<<<(ut + 255) / 256, 256>>>(out1, up, H, W, ut);
    }

    // ================= level 0: C=64, 128x128 =================
    {
        const int H = 128, W = 128, HW = H * W;
        IM2COL(x0, 128, 128L * HW, flow0, 2, 2L * HW, H, W, 136, 1280);
        WCONV(off_w0, 64, 130, 136, 1280, 128);
        GEMM(off_b0, offeat, 1280, 64, 64, HW, 1);

        IM2COL(offeat, 64, 64L * HW, nullptr, 0, 0, H, W, 64, 576);
        WCONV(co_w0, 216, 64, 64, 576, 256);
        GEMM(co_b0, om, 576, 216, 216, HW, 2);

        int st = B * 72 * HW;
        dcn_sample_bf<<<(st + 255) / 256, 256>>>(x0 + 64L * HW, 128L * HW, om,
                                                 (uint4*)Bhi, (uint4*)Blo,
                                                 64, H, W, st);
        WCONV(dcn_w0, 64, 64, 64, 576, 128);
        GEMM(dcn_b0, fuse, 576, 64, 128, HW, 1);

        IM2COL(up, 128, 128L * HW, nullptr, 0, 0, H, W, 128, 1152);
        WCONV(ch_w0, 64, 128, 128, 1152, 128);
        GEMM(ch_b0, fuse + 64L * HW, 1152, 64, 128, HW, 1);

        IM2COL(fuse, 128, 128L * HW, nullptr, 0, 0, H, W, 128, 1152);
        WCONV(ft_w0, 64, 128, 128, 1152, 128);
        GEMM(ft_b0, out0, 1152, 64, 64, HW, 1);
    }
}